// round 4
// baseline (speedup 1.0000x reference)
#include <cuda_runtime.h>
#include <cuda_bf16.h>
#include <cstdint>

#define NN   8192
#define FIN  256
#define FOUT 128
#define L2E  1.44269504f
#define LRA  0.2f
#define CK   64                    // j per chunk
#define JSPLIT 4
#define JBLK (NN / JSPLIT)         // 2048
#define NCH  (JBLK / CK)           // 32 chunks per block
#define RBLK 256                   // rows per block
#define NTI  (NN / CK)             // 128 prebuilt B tiles
#define TERM_BYTES 16384           // one term (hi or lo): 64j x 128d x 2B
#define TILE_BYTES 32768           // hi + lo

__device__ __align__(16)  float g_h[NN * FOUT];
__device__ float g_e1s[NN];        // 1.4427 * e1
__device__ float g_e2s[NN];        // 1.4427 * e2
__device__ __align__(128) unsigned char g_bt[(size_t)NTI * TILE_BYTES];  // 4MB
__device__ __align__(16)  float g_part[JSPLIT][NN * FOUT];               // 16MB
__device__ float g_psum[JSPLIT][NN];

// ------------------------- helpers -----------------------------------------
__device__ __forceinline__ uint32_t smem_u32(const void* p) {
    uint32_t a;
    asm("{ .reg .u64 t; cvta.to.shared.u64 t, %1; cvt.u32.u64 %0, t; }" : "=r"(a) : "l"(p));
    return a;
}
__device__ __forceinline__ uint32_t packbf(float lo, float hi) {
    uint32_t r;  // low 16 bits = lo (element with lower k index)
    asm("cvt.rn.bf16x2.f32 %0, %1, %2;" : "=r"(r) : "f"(hi), "f"(lo));
    return r;
}
__device__ __forceinline__ void split2(float a, float b, uint32_t& hi, uint32_t& lo) {
    hi = packbf(a, b);
    float ra = a - __uint_as_float(hi << 16);
    float rb = b - __uint_as_float(hi & 0xFFFF0000u);
    lo = packbf(ra, rb);
}
__device__ __forceinline__ float pcalc(float se1, float se2, int a) {
    float s = se1 + se2;
    s = fmaxf(s, LRA * s);          // leakyrelu commutes with positive scaling
    float p;
    asm("ex2.approx.f32 %0, %1;" : "=f"(p) : "f"(s));
    return a ? p : 0.f;
}
__device__ __forceinline__ void mma16816(float* c, const uint32_t* a, const uint32_t* b) {
    asm volatile("mma.sync.aligned.m16n8k16.row.col.f32.bf16.bf16.f32 "
        "{%0,%1,%2,%3}, {%4,%5,%6,%7}, {%8,%9}, {%0,%1,%2,%3};"
        : "+f"(c[0]), "+f"(c[1]), "+f"(c[2]), "+f"(c[3])
        : "r"(a[0]), "r"(a[1]), "r"(a[2]), "r"(a[3]), "r"(b[0]), "r"(b[1]));
}
#define LDMX4(r, a) \
    asm volatile("ldmatrix.sync.aligned.m8n8.x4.shared.b16 {%0,%1,%2,%3}, [%4];" \
        : "=r"((r)[0]), "=r"((r)[1]), "=r"((r)[2]), "=r"((r)[3]) : "r"(a))
#define CP_ASYNC(dst, src) \
    asm volatile("cp.async.cg.shared.global [%0], [%1], 16;" :: "r"(dst), "l"(src))
#define CP_COMMIT() asm volatile("cp.async.commit_group;" ::: "memory")
#define CP_WAIT1()  asm volatile("cp.async.wait_group 1;"  ::: "memory")

// ---------------------------------------------------------------------------
// Kernel 1: h = x @ trans
// ---------------------------------------------------------------------------
__global__ __launch_bounds__(256) void k_gemm_h(const float* __restrict__ x,
                                                const float* __restrict__ trans)
{
    __shared__ float xs[64 * 32];
    __shared__ float ts[32 * FOUT];
    const int t = threadIdx.x;
    const int rowbase = blockIdx.x * 64;
    const int ty = t >> 5;
    const int tx = t & 31;

    float acc[8][4];
    #pragma unroll
    for (int i = 0; i < 8; i++)
        #pragma unroll
        for (int c = 0; c < 4; c++) acc[i][c] = 0.f;

    const float4* x4 = (const float4*)x;
    const float4* t4 = (const float4*)trans;

    for (int k0 = 0; k0 < FIN; k0 += 32) {
        #pragma unroll
        for (int v = t, i = 0; i < 2; i++, v += 256) {
            int r = v >> 3, c = v & 7;
            ((float4*)xs)[r * 8 + c] = x4[(size_t)(rowbase + r) * (FIN/4) + (k0 >> 2) + c];
        }
        #pragma unroll
        for (int v = t, i = 0; i < 4; i++, v += 256) {
            int r = v >> 5, c = v & 31;
            ((float4*)ts)[r * 32 + c] = t4[(size_t)(k0 + r) * (FOUT/4) + c];
        }
        __syncthreads();
        #pragma unroll
        for (int kk = 0; kk < 32; kk++) {
            float4 b = *(const float4*)&ts[kk * FOUT + tx * 4];
            #pragma unroll
            for (int i = 0; i < 8; i++) {
                float a = xs[(ty * 8 + i) * 32 + kk];
                acc[i][0] += a * b.x; acc[i][1] += a * b.y;
                acc[i][2] += a * b.z; acc[i][3] += a * b.w;
            }
        }
        __syncthreads();
    }
    #pragma unroll
    for (int i = 0; i < 8; i++) {
        float4 o = make_float4(acc[i][0], acc[i][1], acc[i][2], acc[i][3]);
        *(float4*)&g_h[(size_t)(rowbase + ty * 8 + i) * FOUT + tx * 4] = o;
    }
}

// ---------------------------------------------------------------------------
// Kernel 2: e1/e2 (pre-scaled by log2(e))
// ---------------------------------------------------------------------------
__global__ __launch_bounds__(256) void k_e(const float* __restrict__ aw)
{
    const int row  = blockIdx.x * 8 + (threadIdx.x >> 5);
    const int lane = threadIdx.x & 31;
    float s1 = 0.f, s2 = 0.f;
    #pragma unroll
    for (int d = lane; d < FOUT; d += 32) {
        float v = g_h[(size_t)row * FOUT + d];
        s1 += v * aw[d];
        s2 += v * aw[FOUT + d];
    }
    #pragma unroll
    for (int o = 16; o; o >>= 1) {
        s1 += __shfl_xor_sync(0xFFFFFFFFu, s1, o);
        s2 += __shfl_xor_sync(0xFFFFFFFFu, s2, o);
    }
    if (lane == 0) { g_e1s[row] = s1 * L2E; g_e2s[row] = s2 * L2E; }
}

// ---------------------------------------------------------------------------
// Kernel 3 (prep): build B = h^T tiles as ldmatrix-ready 8x8 b16 blocks.
// blk = ((step*8+dpair)*2+dn)*2+kk, each blk = 128B: 8 rows (dr) x 8 j pairs.
// Element (dr, jc) = h[j0 + step*16 + kk*8 + jc][dpair*16 + dn*8 + dr].
// ---------------------------------------------------------------------------
__global__ __launch_bounds__(256) void k_prep()
{
    const int tc = blockIdx.x;
    const int t  = threadIdx.x;
    const int j0 = tc * CK;
    unsigned char* tb = g_bt + (size_t)tc * TILE_BYTES;

    #pragma unroll
    for (int i = 0; i < 4; i++) {
        int rho = i * 256 + t;
        int blk = rho >> 3, dr = rho & 7;
        int kk = blk & 1, dn = (blk >> 1) & 1, dp = (blk >> 2) & 7, st = blk >> 5;
        int d  = dp * 16 + dn * 8 + dr;
        int jb = j0 + st * 16 + kk * 8;
        uint32_t hi4[4], lo4[4];
        #pragma unroll
        for (int m = 0; m < 4; m++) {
            float a = g_h[(size_t)(jb + 2*m)     * FOUT + d];
            float b = g_h[(size_t)(jb + 2*m + 1) * FOUT + d];
            split2(a, b, hi4[m], lo4[m]);
        }
        uint32_t off = (uint32_t)blk * 128 + dr * 16;
        *(uint4*)(tb + off)              = make_uint4(hi4[0], hi4[1], hi4[2], hi4[3]);
        *(uint4*)(tb + TERM_BYTES + off) = make_uint4(lo4[0], lo4[1], lo4[2], lo4[3]);
    }
}

// ---------------------------------------------------------------------------
// Kernel 4 (main): fused masked-exp + HMMA bf16-split attention GEMM.
// 512 threads = 16 warps = 8 row-groups (m32) x 2 column-halves (n64).
// Each warp: m32 x n64, acc = 64 fp32 regs -> ~120 regs/thread -> full
// 64K regfile with ONE 512-thread CTA = 4 warps/SMSP.
// A fragments in-register (exp duplicated across the 2 col-halves; adj dup
// loads hit L1). B via cp.async double buffer + ldmatrix.x4; 3 bf16 terms.
// ---------------------------------------------------------------------------
__global__ __launch_bounds__(512, 1) void k_main(const int* __restrict__ adj)
{
    extern __shared__ unsigned char smem[];
    const uint32_t sb = smem_u32(smem);
    const int t = threadIdx.x, w = t >> 5, l = t & 31;
    const int rg = w >> 1, cg = w & 1;
    const int bx = blockIdx.x, by = blockIdx.y;
    const int g = l >> 2, q2 = (l & 3) * 2;
    const int rowb = bx * RBLK + rg * 32;
    const size_t jbase = (size_t)by * JBLK;

    // prime B double-buffer (2 x 32KB, 512 threads -> 4 vec16 each per buf)
    const unsigned char* bt0 = g_bt + (size_t)(by * NCH) * TILE_BYTES;
    #pragma unroll
    for (int c = 0; c < 2; c++) {
        uint32_t dst = sb + c * TILE_BYTES + t * 16;
        const unsigned char* src = bt0 + (size_t)c * TILE_BYTES + t * 16;
        #pragma unroll
        for (int i = 0; i < 4; i++) CP_ASYNC(dst + i * 8192, src + i * 8192);
        CP_COMMIT();
    }

    float se1[4];
    const int* rp[4];
    #pragma unroll
    for (int i = 0; i < 4; i++) {
        se1[i] = g_e1s[rowb + g + i * 8];
        rp[i]  = adj + (size_t)(rowb + g + i * 8) * NN;
    }

    float c_[2][8][4];                       // mg x (4 dp' x 2 n8) x 4
    #pragma unroll
    for (int mg = 0; mg < 2; mg++)
        #pragma unroll
        for (int td = 0; td < 8; td++)
            #pragma unroll
            for (int k = 0; k < 4; k++) c_[mg][td][k] = 0.f;
    float rs[4] = {0.f, 0.f, 0.f, 0.f};

    // adj prefetch for (c=0, s=0)
    size_t joff = jbase + q2;
    int2 aA[4], aB[4];
    #pragma unroll
    for (int i = 0; i < 4; i++) {
        aA[i] = __ldg((const int2*)(rp[i] + joff));
        aB[i] = __ldg((const int2*)(rp[i] + joff + 8));
    }

    for (int c = 0; c < NCH; c++) {
        CP_WAIT1();
        __syncthreads();
        const uint32_t bufb = sb + (c & 1) * TILE_BYTES;

        #pragma unroll
        for (int s = 0; s < 4; s++) {
            const float2 e2a = *(const float2*)(g_e2s + joff);
            const float2 e2b = *(const float2*)(g_e2s + joff + 8);

            uint32_t ahi[2][4], alo[2][4];
            #pragma unroll
            for (int i = 0; i < 4; i++) {
                float p0 = pcalc(se1[i], e2a.x, aA[i].x);
                float p1 = pcalc(se1[i], e2a.y, aA[i].y);
                float p2 = pcalc(se1[i], e2b.x, aB[i].x);
                float p3 = pcalc(se1[i], e2b.y, aB[i].y);
                rs[i] += (p0 + p1) + (p2 + p3);
                const int mg = i >> 1, hh = i & 1;
                split2(p0, p1, ahi[mg][hh],     alo[mg][hh]);
                split2(p2, p3, ahi[mg][2 + hh], alo[mg][2 + hh]);
            }

            if (!(c == NCH - 1 && s == 3)) {
                joff += 16;
                #pragma unroll
                for (int i = 0; i < 4; i++) {
                    aA[i] = __ldg((const int2*)(rp[i] + joff));
                    aB[i] = __ldg((const int2*)(rp[i] + joff + 8));
                }
            }

            #pragma unroll
            for (int dp = 0; dp < 4; dp++) {
                uint32_t bh[4], bl[4];
                const uint32_t ad = bufb + (s * 8 + cg * 4 + dp) * 512
                                  + (l >> 3) * 128 + (l & 7) * 16;
                LDMX4(bh, ad);
                LDMX4(bl, ad + TERM_BYTES);
                #pragma unroll
                for (int mg = 0; mg < 2; mg++) {
                    float* c0 = c_[mg][2 * dp];
                    float* c1 = c_[mg][2 * dp + 1];
                    mma16816(c0, ahi[mg], bh);
                    mma16816(c1, ahi[mg], bh + 2);
                    mma16816(c0, alo[mg], bh);
                    mma16816(c1, alo[mg], bh + 2);
                    mma16816(c0, ahi[mg], bl);
                    mma16816(c1, ahi[mg], bl + 2);
                }
            }
        }

        __syncthreads();
        if (c + 2 < NCH) {
            uint32_t dst = sb + (c & 1) * TILE_BYTES + t * 16;
            const unsigned char* src = bt0 + (size_t)(c + 2) * TILE_BYTES + t * 16;
            #pragma unroll
            for (int i = 0; i < 4; i++) CP_ASYNC(dst + i * 8192, src + i * 8192);
        }
        CP_COMMIT();
    }

    // row sums: reduce over the 4 lanes sharing g (cg=0 half writes)
    #pragma unroll
    for (int i = 0; i < 4; i++) {
        rs[i] += __shfl_xor_sync(0xFFFFFFFFu, rs[i], 1);
        rs[i] += __shfl_xor_sync(0xFFFFFFFFu, rs[i], 2);
    }
    if (cg == 0 && (l & 3) == 0) {
        #pragma unroll
        for (int i = 0; i < 4; i++)
            g_psum[by][rowb + g + i * 8] = rs[i];
    }

    // store unnormalized partials (this warp's n64 half)
    float* pb = g_part[by];
    #pragma unroll
    for (int mg = 0; mg < 2; mg++) {
        const int row0 = rowb + mg * 16 + g;
        #pragma unroll
        for (int td = 0; td < 8; td++) {
            const int col = cg * 64 + td * 8 + q2;
            *(float2*)(pb + (size_t)row0 * FOUT + col) =
                make_float2(c_[mg][td][0], c_[mg][td][1]);
            *(float2*)(pb + (size_t)(row0 + 8) * FOUT + col) =
                make_float2(c_[mg][td][2], c_[mg][td][3]);
        }
    }
}

// ---------------------------------------------------------------------------
// Kernel 5 (final): combine j-split partials, normalize, ELU.
// ---------------------------------------------------------------------------
__global__ __launch_bounds__(256) void k_final(float* __restrict__ out)
{
    const int idx = blockIdx.x * 256 + threadIdx.x;   // float4 index
    const int r = idx >> 5;
    float4 v = make_float4(0.f, 0.f, 0.f, 0.f);
    #pragma unroll
    for (int p = 0; p < JSPLIT; p++) {
        float4 a = ((const float4*)g_part[p])[idx];
        v.x += a.x; v.y += a.y; v.z += a.z; v.w += a.w;
    }
    const float inv = 1.f / (g_psum[0][r] + g_psum[1][r] + g_psum[2][r] + g_psum[3][r]);
    float o[4] = { v.x * inv, v.y * inv, v.z * inv, v.w * inv };
    #pragma unroll
    for (int i = 0; i < 4; i++) o[i] = o[i] > 0.f ? o[i] : expm1f(o[i]);
    ((float4*)out)[idx] = make_float4(o[0], o[1], o[2], o[3]);
}

// ---------------------------------------------------------------------------
extern "C" void kernel_launch(void* const* d_in, const int* in_sizes, int n_in,
                              void* d_out, int out_size)
{
    const float* x     = (const float*)d_in[0];
    const int*   adj   = (const int*)d_in[1];
    const float* trans = (const float*)d_in[2];
    const float* aw    = (const float*)d_in[3];
    float*       out   = (float*)d_out;

    const int smem_bytes = 2 * TILE_BYTES;   // 64KB
    cudaFuncSetAttribute(k_main, cudaFuncAttributeMaxDynamicSharedMemorySize, smem_bytes);

    k_gemm_h<<<NN / 64, 256>>>(x, trans);
    k_e<<<NN / 8, 256>>>(aw);
    k_prep<<<NTI, 256>>>();
    dim3 gmain(NN / RBLK, JSPLIT);
    k_main<<<gmain, 512, smem_bytes>>>(adj);
    k_final<<<NN * FOUT / (256 * 4), 256>>>(out);
}

// round 5
// speedup vs baseline: 1.8653x; 1.8653x over previous
#include <cuda_runtime.h>
#include <cuda_fp16.h>
#include <cstdint>

#define NN   8192
#define FIN  256
#define FOUT 128
#define L2E  1.44269504f
#define LRA  0.2f
#define CK   64                    // j per chunk
#define JSPLIT 4
#define JBLK (NN / JSPLIT)         // 2048
#define NCH  (JBLK / CK)           // 32 chunks per block
#define RBLK 256                   // rows per block
#define NTI  (NN / CK)             // 128 prebuilt B tiles
#define TILE_BYTES 16384           // 64j x 128d x 2B (single fp16 term)

__device__ __align__(16)  float g_h[NN * FOUT];
__device__ float g_e1s[NN];        // 1.4427 * e1
__device__ float g_e2s[NN];        // 1.4427 * e2
__device__ __align__(128) unsigned char g_bt[(size_t)NTI * TILE_BYTES];  // 2MB
__device__ __align__(16)  float g_part[JSPLIT][NN * FOUT];               // 16MB
__device__ float g_psum[JSPLIT][NN];

// ------------------------- helpers -----------------------------------------
__device__ __forceinline__ uint32_t smem_u32(const void* p) {
    uint32_t a;
    asm("{ .reg .u64 t; cvta.to.shared.u64 t, %1; cvt.u32.u64 %0, t; }" : "=r"(a) : "l"(p));
    return a;
}
__device__ __forceinline__ uint32_t pack16(float lo, float hi) {
    uint32_t r;  // low 16 bits = lo (lower k index)
    asm("cvt.rn.f16x2.f32 %0, %1, %2;" : "=r"(r) : "f"(hi), "f"(lo));
    return r;
}
__device__ __forceinline__ float pcalc(float se1, float se2, uint32_t f) {
    float s = se1 + se2;
    s = fmaxf(s, LRA * s) - 3.0f;   // lrelu (commutes with +scale), fp16-safety shift
    float p;
    asm("ex2.approx.f32 %0, %1;" : "=f"(p) : "f"(s));
    return f ? p : 0.f;
}
__device__ __forceinline__ void mma16816(float* c, const uint32_t* a, const uint32_t* b) {
    asm volatile("mma.sync.aligned.m16n8k16.row.col.f32.f16.f16.f32 "
        "{%0,%1,%2,%3}, {%4,%5,%6,%7}, {%8,%9}, {%0,%1,%2,%3};"
        : "+f"(c[0]), "+f"(c[1]), "+f"(c[2]), "+f"(c[3])
        : "r"(a[0]), "r"(a[1]), "r"(a[2]), "r"(a[3]), "r"(b[0]), "r"(b[1]));
}
#define LDMX4(r, a) \
    asm volatile("ldmatrix.sync.aligned.m8n8.x4.shared.b16 {%0,%1,%2,%3}, [%4];" \
        : "=r"((r)[0]), "=r"((r)[1]), "=r"((r)[2]), "=r"((r)[3]) : "r"(a))
#define CP_ASYNC(dst, src) \
    asm volatile("cp.async.cg.shared.global [%0], [%1], 16;" :: "r"(dst), "l"(src))
#define CP_COMMIT() asm volatile("cp.async.commit_group;" ::: "memory")
#define CP_WAIT1()  asm volatile("cp.async.wait_group 1;"  ::: "memory")

// ---------------------------------------------------------------------------
// Kernel 1: h = x @ trans
// ---------------------------------------------------------------------------
__global__ __launch_bounds__(256) void k_gemm_h(const float* __restrict__ x,
                                                const float* __restrict__ trans)
{
    __shared__ float xs[64 * 32];
    __shared__ float ts[32 * FOUT];
    const int t = threadIdx.x;
    const int rowbase = blockIdx.x * 64;
    const int ty = t >> 5;
    const int tx = t & 31;

    float acc[8][4];
    #pragma unroll
    for (int i = 0; i < 8; i++)
        #pragma unroll
        for (int c = 0; c < 4; c++) acc[i][c] = 0.f;

    const float4* x4 = (const float4*)x;
    const float4* t4 = (const float4*)trans;

    for (int k0 = 0; k0 < FIN; k0 += 32) {
        #pragma unroll
        for (int v = t, i = 0; i < 2; i++, v += 256) {
            int r = v >> 3, c = v & 7;
            ((float4*)xs)[r * 8 + c] = x4[(size_t)(rowbase + r) * (FIN/4) + (k0 >> 2) + c];
        }
        #pragma unroll
        for (int v = t, i = 0; i < 4; i++, v += 256) {
            int r = v >> 5, c = v & 31;
            ((float4*)ts)[r * 32 + c] = t4[(size_t)(k0 + r) * (FOUT/4) + c];
        }
        __syncthreads();
        #pragma unroll
        for (int kk = 0; kk < 32; kk++) {
            float4 b = *(const float4*)&ts[kk * FOUT + tx * 4];
            #pragma unroll
            for (int i = 0; i < 8; i++) {
                float a = xs[(ty * 8 + i) * 32 + kk];
                acc[i][0] += a * b.x; acc[i][1] += a * b.y;
                acc[i][2] += a * b.z; acc[i][3] += a * b.w;
            }
        }
        __syncthreads();
    }
    #pragma unroll
    for (int i = 0; i < 8; i++) {
        float4 o = make_float4(acc[i][0], acc[i][1], acc[i][2], acc[i][3]);
        *(float4*)&g_h[(size_t)(rowbase + ty * 8 + i) * FOUT + tx * 4] = o;
    }
}

// ---------------------------------------------------------------------------
// Kernel 2: e1/e2 (pre-scaled by log2(e))
// ---------------------------------------------------------------------------
__global__ __launch_bounds__(256) void k_e(const float* __restrict__ aw)
{
    const int row  = blockIdx.x * 8 + (threadIdx.x >> 5);
    const int lane = threadIdx.x & 31;
    float s1 = 0.f, s2 = 0.f;
    #pragma unroll
    for (int d = lane; d < FOUT; d += 32) {
        float v = g_h[(size_t)row * FOUT + d];
        s1 += v * aw[d];
        s2 += v * aw[FOUT + d];
    }
    #pragma unroll
    for (int o = 16; o; o >>= 1) {
        s1 += __shfl_xor_sync(0xFFFFFFFFu, s1, o);
        s2 += __shfl_xor_sync(0xFFFFFFFFu, s2, o);
    }
    if (lane == 0) { g_e1s[row] = s1 * L2E; g_e2s[row] = s2 * L2E; }
}

// ---------------------------------------------------------------------------
// Kernel 3 (prep): build B = h^T tiles (single fp16) as ldmatrix-ready 8x8
// b16 blocks. blk = ((step*8+dpair)*2+dn)*2+kk; each blk = 128B: 8 rows (dr)
// x 8 j (fp16 pairs). Element (dr, jc) = h[j0+step*16+kk*8+jc][dp*16+dn*8+dr].
// ---------------------------------------------------------------------------
__global__ __launch_bounds__(256) void k_prep()
{
    const int tc = blockIdx.x;
    const int t  = threadIdx.x;
    const int j0 = tc * CK;
    unsigned char* tb = g_bt + (size_t)tc * TILE_BYTES;

    #pragma unroll
    for (int i = 0; i < 4; i++) {
        int rho = i * 256 + t;
        int blk = rho >> 3, dr = rho & 7;
        int kk = blk & 1, dn = (blk >> 1) & 1, dp = (blk >> 2) & 7, st = blk >> 5;
        int d  = dp * 16 + dn * 8 + dr;
        int jb = j0 + st * 16 + kk * 8;
        uint32_t h4[4];
        #pragma unroll
        for (int m = 0; m < 4; m++) {
            float a = g_h[(size_t)(jb + 2*m)     * FOUT + d];
            float b = g_h[(size_t)(jb + 2*m + 1) * FOUT + d];
            h4[m] = pack16(a, b);
        }
        *(uint4*)(tb + (uint32_t)blk * 128 + dr * 16) =
            make_uint4(h4[0], h4[1], h4[2], h4[3]);
    }
}

// ---------------------------------------------------------------------------
// Kernel 4 (main): fused masked-exp + single-term fp16 HMMA attention GEMM.
// 512 threads = 16 warps = 16 row-groups of m16; each warp m16 x n128.
// adj: warp-cooperative coalesced int2 loads + ballot -> per-lane bitmasks.
// A (p in fp16) built in-register in fragment layout; B (h^T fp16) via
// cp.async double buffer + ldmatrix.x4.
// ---------------------------------------------------------------------------
__global__ __launch_bounds__(512, 1) void k_main(const int* __restrict__ adj)
{
    extern __shared__ unsigned char smem[];
    const uint32_t sb = smem_u32(smem);
    const int t = threadIdx.x, w = t >> 5, l = t & 31;
    const int bx = blockIdx.x, by = blockIdx.y;
    const int g = l >> 2, qh = l & 3, q2 = qh * 2;
    const int rowb = bx * RBLK + w * 16;
    const size_t jbase = (size_t)by * JBLK;

    // prime B double-buffer
    const unsigned char* bt0 = g_bt + (size_t)(by * NCH) * TILE_BYTES;
    #pragma unroll
    for (int c = 0; c < 2; c++) {
        uint32_t dst = sb + c * TILE_BYTES + t * 16;
        const unsigned char* src = bt0 + (size_t)c * TILE_BYTES + t * 16;
        CP_ASYNC(dst, src);
        CP_ASYNC(dst + 8192, src + 8192);
        CP_COMMIT();
    }

    const float se1g = g_e1s[rowb + g];
    const float se1h = g_e1s[rowb + g + 8];
    const int* arow = adj + (size_t)rowb * NN + jbase;

    float c_[16][4];
    #pragma unroll
    for (int td = 0; td < 16; td++)
        #pragma unroll
        for (int k = 0; k < 4; k++) c_[td][k] = 0.f;
    float rs0 = 0.f, rs1 = 0.f;

    for (int c = 0; c < NCH; c++) {
        const int jc = c * CK;

        // ---- adj: coalesced loads + ballot pack ----
        // lane reads adj[row r][jc + 2l, 2l+1]; ballot bit l = flag(j = jc+2l(+1))
        int2 v[16];
        #pragma unroll
        for (int r = 0; r < 16; r++)
            v[r] = __ldg((const int2*)(arow + (size_t)r * NN + jc) + l);
        uint32_t ml0 = 0, ml1 = 0, mh0 = 0, mh1 = 0;
        #pragma unroll
        for (int r = 0; r < 16; r++) {
            uint32_t b0 = __ballot_sync(0xFFFFFFFFu, v[r].x != 0);
            uint32_t b1 = __ballot_sync(0xFFFFFFFFu, v[r].y != 0);
            ml0 = (r == g)     ? b0 : ml0;
            ml1 = (r == g)     ? b1 : ml1;
            mh0 = (r == g + 8) ? b0 : mh0;
            mh1 = (r == g + 8) ? b1 : mh1;
        }

        CP_WAIT1();
        __syncthreads();
        const uint32_t bufb = sb + (c & 1) * TILE_BYTES;

        #pragma unroll
        for (int s = 0; s < 4; s++) {
            const size_t joff = jbase + jc + 16 * s + q2;
            const float2 e2a = *(const float2*)(g_e2s + joff);
            const float2 e2b = *(const float2*)(g_e2s + joff + 8);

            // bit index for (j = 16s + q2 + {0,1,8,9}): (8s+qh) in b0/b1, +4 for +8
            const int bs = 8 * s + qh;
            float p00 = pcalc(se1g, e2a.x, (ml0 >> bs) & 1u);
            float p01 = pcalc(se1g, e2a.y, (ml1 >> bs) & 1u);
            float p08 = pcalc(se1g, e2b.x, (ml0 >> (bs + 4)) & 1u);
            float p09 = pcalc(se1g, e2b.y, (ml1 >> (bs + 4)) & 1u);
            float p10 = pcalc(se1h, e2a.x, (mh0 >> bs) & 1u);
            float p11 = pcalc(se1h, e2a.y, (mh1 >> bs) & 1u);
            float p18 = pcalc(se1h, e2b.x, (mh0 >> (bs + 4)) & 1u);
            float p19 = pcalc(se1h, e2b.y, (mh1 >> (bs + 4)) & 1u);
            rs0 += (p00 + p01) + (p08 + p09);
            rs1 += (p10 + p11) + (p18 + p19);

            uint32_t a[4];
            a[0] = pack16(p00, p01);
            a[1] = pack16(p10, p11);
            a[2] = pack16(p08, p09);
            a[3] = pack16(p18, p19);

            #pragma unroll
            for (int dp = 0; dp < 8; dp++) {
                uint32_t bh[4];
                const uint32_t ad = bufb + (s * 8 + dp) * 512
                                  + (l >> 3) * 128 + (l & 7) * 16;
                LDMX4(bh, ad);
                mma16816(c_[2 * dp],     a, bh);
                mma16816(c_[2 * dp + 1], a, bh + 2);
            }
        }

        __syncthreads();
        if (c + 2 < NCH) {
            uint32_t dst = sb + (c & 1) * TILE_BYTES + t * 16;
            const unsigned char* src = bt0 + (size_t)(c + 2) * TILE_BYTES + t * 16;
            CP_ASYNC(dst, src);
            CP_ASYNC(dst + 8192, src + 8192);
        }
        CP_COMMIT();
    }

    // row sums: reduce over 4 lanes sharing g
    rs0 += __shfl_xor_sync(0xFFFFFFFFu, rs0, 1);
    rs0 += __shfl_xor_sync(0xFFFFFFFFu, rs0, 2);
    rs1 += __shfl_xor_sync(0xFFFFFFFFu, rs1, 1);
    rs1 += __shfl_xor_sync(0xFFFFFFFFu, rs1, 2);
    if (qh == 0) {
        g_psum[by][rowb + g]     = rs0;
        g_psum[by][rowb + g + 8] = rs1;
    }

    // store unnormalized partials
    float* pb = g_part[by];
    #pragma unroll
    for (int td = 0; td < 16; td++) {
        const int col = td * 8 + q2;
        *(float2*)(pb + (size_t)(rowb + g) * FOUT + col) =
            make_float2(c_[td][0], c_[td][1]);
        *(float2*)(pb + (size_t)(rowb + g + 8) * FOUT + col) =
            make_float2(c_[td][2], c_[td][3]);
    }
}

// ---------------------------------------------------------------------------
// Kernel 5 (final): combine j-split partials, normalize, ELU.
// ---------------------------------------------------------------------------
__global__ __launch_bounds__(256) void k_final(float* __restrict__ out)
{
    const int idx = blockIdx.x * 256 + threadIdx.x;   // float4 index
    const int r = idx >> 5;
    float4 v = make_float4(0.f, 0.f, 0.f, 0.f);
    #pragma unroll
    for (int p = 0; p < JSPLIT; p++) {
        float4 a = ((const float4*)g_part[p])[idx];
        v.x += a.x; v.y += a.y; v.z += a.z; v.w += a.w;
    }
    const float inv = 1.f / (g_psum[0][r] + g_psum[1][r] + g_psum[2][r] + g_psum[3][r]);
    float o[4] = { v.x * inv, v.y * inv, v.z * inv, v.w * inv };
    #pragma unroll
    for (int i = 0; i < 4; i++) o[i] = o[i] > 0.f ? o[i] : expm1f(o[i]);
    ((float4*)out)[idx] = make_float4(o[0], o[1], o[2], o[3]);
}

// ---------------------------------------------------------------------------
extern "C" void kernel_launch(void* const* d_in, const int* in_sizes, int n_in,
                              void* d_out, int out_size)
{
    const float* x     = (const float*)d_in[0];
    const int*   adj   = (const int*)d_in[1];
    const float* trans = (const float*)d_in[2];
    const float* aw    = (const float*)d_in[3];
    float*       out   = (float*)d_out;

    const int smem_bytes = 2 * TILE_BYTES;   // 32KB
    cudaFuncSetAttribute(k_main, cudaFuncAttributeMaxDynamicSharedMemorySize, smem_bytes);

    k_gemm_h<<<NN / 64, 256>>>(x, trans);
    k_e<<<NN / 8, 256>>>(aw);
    k_prep<<<NTI, 256>>>();
    dim3 gmain(NN / RBLK, JSPLIT);
    k_main<<<gmain, 512, smem_bytes>>>(adj);
    k_final<<<NN * FOUT / (256 * 4), 256>>>(out);
}

// round 6
// speedup vs baseline: 1.9130x; 1.0256x over previous
#include <cuda_runtime.h>
#include <cuda_fp16.h>
#include <cstdint>

#define NN   8192
#define FIN  256
#define FOUT 128
#define L2E  1.44269504f
#define LRA  0.2f
#define CK   64                    // j per chunk
#define JSPLIT 4
#define JBLK (NN / JSPLIT)         // 2048
#define NCH  (JBLK / CK)           // 32 chunks per block
#define RBLK 256                   // rows per block
#define NTI  (NN / CK)             // 128 prebuilt B tiles
#define TILE_BYTES 16384           // 64j x 128d x 2B (single fp16 term)

__device__ __align__(16)  float g_h[NN * FOUT];
__device__ float g_e1s[NN];        // 1.4427 * e1
__device__ float g_e2s[NN];        // 1.4427 * e2
__device__ __align__(128) unsigned char g_bt[(size_t)NTI * TILE_BYTES];  // 2MB
__device__ __align__(16)  float g_part[JSPLIT][NN * FOUT];               // 16MB
__device__ float g_psum[JSPLIT][NN];

// ------------------------- helpers -----------------------------------------
__device__ __forceinline__ uint32_t smem_u32(const void* p) {
    uint32_t a;
    asm("{ .reg .u64 t; cvta.to.shared.u64 t, %1; cvt.u32.u64 %0, t; }" : "=r"(a) : "l"(p));
    return a;
}
__device__ __forceinline__ uint32_t pack16(float lo, float hi) {
    uint32_t r;  // low 16 bits = lo (lower k index)
    asm("cvt.rn.f16x2.f32 %0, %1, %2;" : "=r"(r) : "f"(hi), "f"(lo));
    return r;
}
// mask-multiply: adj ints (0/1) -> fp16x2 {0,1} mask via 2 IMADs, one mul.f16x2
__device__ __forceinline__ uint32_t packmask(float lo, float hi, int ax, int ay) {
    uint32_t p = pack16(lo, hi);
    uint32_t m = (uint32_t)ax * 0x3C00u + (uint32_t)ay * 0x3C000000u;
    uint32_t r;
    asm("mul.f16x2 %0, %1, %2;" : "=r"(r) : "r"(p), "r"(m));
    return r;
}
__device__ __forceinline__ float pcalc(float se1, float se2) {
    float s = se1 + se2;
    s = fmaxf(s, LRA * s);          // lrelu commutes with positive scale
    float p;
    asm("ex2.approx.f32 %0, %1;" : "=f"(p) : "f"(s));
    return p;
}
__device__ __forceinline__ void mma16816(float* c, const uint32_t* a, const uint32_t* b) {
    asm volatile("mma.sync.aligned.m16n8k16.row.col.f32.f16.f16.f32 "
        "{%0,%1,%2,%3}, {%4,%5,%6,%7}, {%8,%9}, {%0,%1,%2,%3};"
        : "+f"(c[0]), "+f"(c[1]), "+f"(c[2]), "+f"(c[3])
        : "r"(a[0]), "r"(a[1]), "r"(a[2]), "r"(a[3]), "r"(b[0]), "r"(b[1]));
}
#define LDMX4(r, a) \
    asm volatile("ldmatrix.sync.aligned.m8n8.x4.shared.b16 {%0,%1,%2,%3}, [%4];" \
        : "=r"((r)[0]), "=r"((r)[1]), "=r"((r)[2]), "=r"((r)[3]) : "r"(a))
#define CP_ASYNC(dst, src) \
    asm volatile("cp.async.cg.shared.global [%0], [%1], 16;" :: "r"(dst), "l"(src))
#define CP_COMMIT() asm volatile("cp.async.commit_group;" ::: "memory")
#define CP_WAIT1()  asm volatile("cp.async.wait_group 1;"  ::: "memory")

// ---------------------------------------------------------------------------
// Kernel 1: h = x @ trans  (32-row tiles, 256 CTAs -> ~2 CTAs/SM)
// ---------------------------------------------------------------------------
__global__ __launch_bounds__(256) void k_gemm_h(const float* __restrict__ x,
                                                const float* __restrict__ trans)
{
    __shared__ float xs[32 * 32];
    __shared__ float ts[32 * FOUT];
    const int t = threadIdx.x;
    const int rowbase = blockIdx.x * 32;
    const int ty = t >> 5;   // 8 groups of 4 rows
    const int tx = t & 31;

    float acc[4][4];
    #pragma unroll
    for (int i = 0; i < 4; i++)
        #pragma unroll
        for (int c = 0; c < 4; c++) acc[i][c] = 0.f;

    const float4* x4 = (const float4*)x;
    const float4* t4 = (const float4*)trans;

    for (int k0 = 0; k0 < FIN; k0 += 32) {
        {   // 256 float4 of x
            int r = t >> 3, c = t & 7;
            ((float4*)xs)[r * 8 + c] = x4[(size_t)(rowbase + r) * (FIN/4) + (k0 >> 2) + c];
        }
        #pragma unroll
        for (int v = t, i = 0; i < 4; i++, v += 256) {   // 1024 float4 of trans
            int r = v >> 5, c = v & 31;
            ((float4*)ts)[r * 32 + c] = t4[(size_t)(k0 + r) * (FOUT/4) + c];
        }
        __syncthreads();
        #pragma unroll
        for (int kk = 0; kk < 32; kk++) {
            float4 b = *(const float4*)&ts[kk * FOUT + tx * 4];
            #pragma unroll
            for (int i = 0; i < 4; i++) {
                float a = xs[(ty * 4 + i) * 32 + kk];
                acc[i][0] += a * b.x; acc[i][1] += a * b.y;
                acc[i][2] += a * b.z; acc[i][3] += a * b.w;
            }
        }
        __syncthreads();
    }
    #pragma unroll
    for (int i = 0; i < 4; i++) {
        float4 o = make_float4(acc[i][0], acc[i][1], acc[i][2], acc[i][3]);
        *(float4*)&g_h[(size_t)(rowbase + ty * 4 + i) * FOUT + tx * 4] = o;
    }
}

// ---------------------------------------------------------------------------
// Kernel 2: e1/e2 (pre-scaled by log2(e))
// ---------------------------------------------------------------------------
__global__ __launch_bounds__(256) void k_e(const float* __restrict__ aw)
{
    const int row  = blockIdx.x * 8 + (threadIdx.x >> 5);
    const int lane = threadIdx.x & 31;
    float s1 = 0.f, s2 = 0.f;
    #pragma unroll
    for (int d = lane; d < FOUT; d += 32) {
        float v = g_h[(size_t)row * FOUT + d];
        s1 += v * aw[d];
        s2 += v * aw[FOUT + d];
    }
    #pragma unroll
    for (int o = 16; o; o >>= 1) {
        s1 += __shfl_xor_sync(0xFFFFFFFFu, s1, o);
        s2 += __shfl_xor_sync(0xFFFFFFFFu, s2, o);
    }
    if (lane == 0) { g_e1s[row] = s1 * L2E; g_e2s[row] = s2 * L2E; }
}

// ---------------------------------------------------------------------------
// Kernel 3 (prep): build B = h^T tiles (fp16) as ldmatrix-ready 8x8 blocks.
// blk = ((step*8+dpair)*2+dn)*2+kk; each blk = 128B: 8 rows (dr) x 8 j.
// Element (dr, jc) = h[j0+step*16+kk*8+jc][dp*16+dn*8+dr].
// ---------------------------------------------------------------------------
__global__ __launch_bounds__(256) void k_prep()
{
    const int tc = blockIdx.x;
    const int t  = threadIdx.x;
    const int j0 = tc * CK;
    unsigned char* tb = g_bt + (size_t)tc * TILE_BYTES;

    #pragma unroll
    for (int i = 0; i < 4; i++) {
        int rho = i * 256 + t;
        int blk = rho >> 3, dr = rho & 7;
        int kk = blk & 1, dn = (blk >> 1) & 1, dp = (blk >> 2) & 7, st = blk >> 5;
        int d  = dp * 16 + dn * 8 + dr;
        int jb = j0 + st * 16 + kk * 8;
        uint32_t h4[4];
        #pragma unroll
        for (int m = 0; m < 4; m++) {
            float a = g_h[(size_t)(jb + 2*m)     * FOUT + d];
            float b = g_h[(size_t)(jb + 2*m + 1) * FOUT + d];
            h4[m] = pack16(a, b);
        }
        *(uint4*)(tb + (uint32_t)blk * 128 + dr * 16) =
            make_uint4(h4[0], h4[1], h4[2], h4[3]);
    }
}

// ---------------------------------------------------------------------------
// Kernel 4 (main): fused masked-exp + fp16 HMMA attention GEMM.
// 512 threads = 16 warps = 16 m16 row-groups; each warp m16 x n128.
// adj: direct int2 loads (sector-optimal), mask via IMAD->fp16x2 multiply.
// Row sums via extra ones-column MMA (fp32 accumulator, no shuffles).
// B (h^T fp16) via cp.async double buffer + ldmatrix.x4.
// ---------------------------------------------------------------------------
__global__ __launch_bounds__(512, 1) void k_main(const int* __restrict__ adj)
{
    extern __shared__ unsigned char smem[];
    const uint32_t sb = smem_u32(smem);
    const int t = threadIdx.x, w = t >> 5, l = t & 31;
    const int bx = blockIdx.x, by = blockIdx.y;
    const int g = l >> 2, qh = l & 3, q2 = qh * 2;
    const int rowb = bx * RBLK + w * 16;
    const size_t jbase = (size_t)by * JBLK;

    // prime B double-buffer
    const unsigned char* bt0 = g_bt + (size_t)(by * NCH) * TILE_BYTES;
    #pragma unroll
    for (int c = 0; c < 2; c++) {
        uint32_t dst = sb + c * TILE_BYTES + t * 16;
        const unsigned char* src = bt0 + (size_t)c * TILE_BYTES + t * 16;
        CP_ASYNC(dst, src);
        CP_ASYNC(dst + 8192, src + 8192);
        CP_COMMIT();
    }

    const float se1g = g_e1s[rowb + g];
    const float se1h = g_e1s[rowb + g + 8];
    const int* pg = adj + (size_t)(rowb + g) * NN + jbase;
    const int* ph = adj + (size_t)(rowb + g + 8) * NN + jbase;

    float c_[16][4];
    #pragma unroll
    for (int td = 0; td < 16; td++)
        #pragma unroll
        for (int k = 0; k < 4; k++) c_[td][k] = 0.f;
    float crs[4] = {0.f, 0.f, 0.f, 0.f};          // ones-MMA row sums
    const uint32_t bones[2] = {0x3C003C00u, 0x3C003C00u};

    // adj prefetch for (c=0, s=0)
    size_t joff = q2;
    int2 av0 = __ldg((const int2*)(pg + joff));
    int2 av1 = __ldg((const int2*)(ph + joff));
    int2 av2 = __ldg((const int2*)(pg + joff + 8));
    int2 av3 = __ldg((const int2*)(ph + joff + 8));

    for (int c = 0; c < NCH; c++) {
        CP_WAIT1();
        __syncthreads();
        const uint32_t bufb = sb + (c & 1) * TILE_BYTES;

        #pragma unroll
        for (int s = 0; s < 4; s++) {
            const float2 e2a = *(const float2*)(g_e2s + jbase + joff);
            const float2 e2b = *(const float2*)(g_e2s + jbase + joff + 8);

            // snapshot adj regs, then prefetch next step early
            const int2 b0 = av0, b1 = av1, b2 = av2, b3 = av3;
            if (!(c == NCH - 1 && s == 3)) {
                joff += 16;
                av0 = __ldg((const int2*)(pg + joff));
                av1 = __ldg((const int2*)(ph + joff));
                av2 = __ldg((const int2*)(pg + joff + 8));
                av3 = __ldg((const int2*)(ph + joff + 8));
            }

            // fp32 exp, fp16 pack, mask-multiply
            float p00 = pcalc(se1g, e2a.x), p01 = pcalc(se1g, e2a.y);
            float p10 = pcalc(se1h, e2a.x), p11 = pcalc(se1h, e2a.y);
            float p08 = pcalc(se1g, e2b.x), p09 = pcalc(se1g, e2b.y);
            float p18 = pcalc(se1h, e2b.x), p19 = pcalc(se1h, e2b.y);

            uint32_t a[4];
            a[0] = packmask(p00, p01, b0.x, b0.y);
            a[1] = packmask(p10, p11, b1.x, b1.y);
            a[2] = packmask(p08, p09, b2.x, b2.y);
            a[3] = packmask(p18, p19, b3.x, b3.y);

            #pragma unroll
            for (int dp = 0; dp < 8; dp++) {
                uint32_t bh[4];
                const uint32_t ad = bufb + (s * 8 + dp) * 512
                                  + (l >> 3) * 128 + (l & 7) * 16;
                LDMX4(bh, ad);
                mma16816(c_[2 * dp],     a, bh);
                mma16816(c_[2 * dp + 1], a, bh + 2);
            }
            mma16816(crs, a, bones);   // row-sum column
        }

        __syncthreads();
        if (c + 2 < NCH) {
            uint32_t dst = sb + (c & 1) * TILE_BYTES + t * 16;
            const unsigned char* src = bt0 + (size_t)(c + 2) * TILE_BYTES + t * 16;
            CP_ASYNC(dst, src);
            CP_ASYNC(dst + 8192, src + 8192);
        }
        CP_COMMIT();
    }

    // row sums: every lane holds them (all n8 cols identical); qh==0 writes
    if (qh == 0) {
        g_psum[by][rowb + g]     = crs[0];
        g_psum[by][rowb + g + 8] = crs[2];
    }

    // store unnormalized partials
    float* pb = g_part[by];
    #pragma unroll
    for (int td = 0; td < 16; td++) {
        const int col = td * 8 + q2;
        *(float2*)(pb + (size_t)(rowb + g) * FOUT + col) =
            make_float2(c_[td][0], c_[td][1]);
        *(float2*)(pb + (size_t)(rowb + g + 8) * FOUT + col) =
            make_float2(c_[td][2], c_[td][3]);
    }
}

// ---------------------------------------------------------------------------
// Kernel 5 (final): combine j-split partials, normalize, ELU.
// ---------------------------------------------------------------------------
__global__ __launch_bounds__(256) void k_final(float* __restrict__ out)
{
    const int idx = blockIdx.x * 256 + threadIdx.x;   // float4 index
    const int r = idx >> 5;
    float4 v = make_float4(0.f, 0.f, 0.f, 0.f);
    #pragma unroll
    for (int p = 0; p < JSPLIT; p++) {
        float4 a = ((const float4*)g_part[p])[idx];
        v.x += a.x; v.y += a.y; v.z += a.z; v.w += a.w;
    }
    const float inv = 1.f / (g_psum[0][r] + g_psum[1][r] + g_psum[2][r] + g_psum[3][r]);
    float o[4] = { v.x * inv, v.y * inv, v.z * inv, v.w * inv };
    #pragma unroll
    for (int i = 0; i < 4; i++) o[i] = o[i] > 0.f ? o[i] : expm1f(o[i]);
    ((float4*)out)[idx] = make_float4(o[0], o[1], o[2], o[3]);
}

// ---------------------------------------------------------------------------
extern "C" void kernel_launch(void* const* d_in, const int* in_sizes, int n_in,
                              void* d_out, int out_size)
{
    const float* x     = (const float*)d_in[0];
    const int*   adj   = (const int*)d_in[1];
    const float* trans = (const float*)d_in[2];
    const float* aw    = (const float*)d_in[3];
    float*       out   = (float*)d_out;

    const int smem_bytes = 2 * TILE_BYTES;   // 32KB
    cudaFuncSetAttribute(k_main, cudaFuncAttributeMaxDynamicSharedMemorySize, smem_bytes);

    k_gemm_h<<<NN / 32, 256>>>(x, trans);
    k_e<<<NN / 8, 256>>>(aw);
    k_prep<<<NTI, 256>>>();
    dim3 gmain(NN / RBLK, JSPLIT);
    k_main<<<gmain, 512, smem_bytes>>>(adj);
    k_final<<<NN * FOUT / (256 * 4), 256>>>(out);
}